// round 10
// baseline (speedup 1.0000x reference)
#include <cuda_runtime.h>
#include <math.h>

// Problem constants
#define BSZ 32
#define SSZ 1024
#define DSZ 1024

typedef unsigned long long ull;

// Scratch buffers (device globals — no allocation allowed in kernel_launch).
// buf0: Z0 (= x@W0) -> overwritten in place with h0 (time-major [S,B,D])
// buf1: Z1 (= h0@W1) (time-major [S,B,D])
__device__ float g_buf0[(size_t)BSZ * SSZ * DSZ];
__device__ float g_buf1[(size_t)BSZ * SSZ * DSZ];
// Paired h state, double-buffered by step parity:
// g_hp[p][b][2*j+0] = h[j], g_hp[p][b][2*j+1] = h[j+512]  (j in 0..511)
__device__ float g_hp[2][BSZ][2 * (DSZ / 2) * 2 / 2];  // [2][32][1024]

// Grid barrier state (zero-initialized; restored at end of each launch).
__device__ unsigned g_bar_count;
__device__ unsigned g_bar_flag;

// ---------------------------------------------------------------------------
// Packed f32x2 helpers (sm_100+). Each lane is an independent IEEE fp32 FMA —
// bit-identical to two scalar fmaf chains.
// ---------------------------------------------------------------------------
__device__ __forceinline__ ull fma2(ull a, ull b, ull c) {
    ull d;
    asm("fma.rn.f32x2 %0, %1, %2, %3;" : "=l"(d) : "l"(a), "l"(b), "l"(c));
    return d;
}
__device__ __forceinline__ void unpack2(ull v, float& lo, float& hi) {
    asm("mov.b64 {%0, %1}, %2;" : "=f"(lo), "=f"(hi) : "l"(v));
}

// ---------------------------------------------------------------------------
// Identified reference arithmetic (validated round 8, lane b10-14):
//   dot = split-K=2: two ascending fp32 fmaf chains of 512, combined s0+s1 (rn)
//   z   = (x@W + h@U) + b   (rn adds in that order)
//   tanh = XLA fast-tanh, with_fma: clamp +-7.99881172180175781, FMA Horner,
//          rn divide, |x|<0.0004 passthrough.
// ---------------------------------------------------------------------------
__device__ __forceinline__ float xla_tanh(float x) {
    const float kMax = 7.99881172180175781f;
    float ax = fabsf(x);
    float xc = fminf(fmaxf(x, -kMax), kMax);
    float x2 = __fmul_rn(xc, xc);
    float p = -2.76076847742355e-16f;
    p = fmaf(x2, p, 2.00018790482477e-13f);
    p = fmaf(x2, p, -8.60467152213735e-11f);
    p = fmaf(x2, p, 5.12229709037114e-08f);
    p = fmaf(x2, p, 1.48572235717979e-05f);
    p = fmaf(x2, p, 6.37261928875436e-04f);
    p = fmaf(x2, p, 4.89352455891786e-03f);
    p = __fmul_rn(xc, p);
    float q = 1.19825839466702e-06f;
    q = fmaf(x2, q, 1.18534705686654e-04f);
    q = fmaf(x2, q, 2.26843463243900e-03f);
    q = fmaf(x2, q, 4.89352518554385e-03f);
    float r = __fdiv_rn(p, q);
    return (ax < 0.0004f) ? x : r;
}

// ---------------------------------------------------------------------------
// Big parallel GEMM: C = A @ W (no bias), split-K=2 arithmetic: per element,
// ascending fmaf chain k=0..511, flush (rn-add), chain k=512..1023, final add.
//   remap=1: A row m = b*S + s  ->  C row = s*B + b   (x -> time-major Z0)
//   remap=0: C row = m
// BM=128, BN=64, BK=8, 256 threads, 8x4 per-thread tile.
// ---------------------------------------------------------------------------
__global__ __launch_bounds__(256) void gemm_kernel(
    const float* __restrict__ A_ext, int a_sel,
    const float* __restrict__ W,
    int c_sel, int remap)
{
    const int N_ = DSZ, K_ = DSZ;
    const float* A = (a_sel == 0) ? (const float*)g_buf0 : A_ext;
    float* C = (c_sel == 0) ? g_buf0 : g_buf1;

    __shared__ float As[8][132];   // [k][m], padded
    __shared__ float Bs[8][64];    // [k][n]

    const int tid = threadIdx.x;
    const int tx = tid & 15;        // 16 col-groups (4 cols each)
    const int ty = tid >> 4;        // 16 row-groups (8 rows each)
    const int m0 = blockIdx.y * 128;
    const int n0 = blockIdx.x * 64;

    float tot[8][4], blk[8][4];
#pragma unroll
    for (int i = 0; i < 8; i++)
#pragma unroll
        for (int j = 0; j < 4; j++) { tot[i][j] = 0.f; blk[i][j] = 0.f; }

    for (int kt = 0; kt < K_; kt += 8) {
        // split-K boundary: flush chain 0 at k = 512
        if (kt == 512) {
#pragma unroll
            for (int i = 0; i < 8; i++)
#pragma unroll
                for (int j = 0; j < 4; j++) {
                    tot[i][j] = blk[i][j];
                    blk[i][j] = 0.f;
                }
        }

        // Load A tile: 128 rows x 8 k (256 float4, 1 per thread), transpose
        {
            int row = tid >> 1;                 // 0..127
            int kq = (tid & 1) * 4;             // 0 or 4
            float4 v = *(const float4*)&A[(size_t)(m0 + row) * K_ + kt + kq];
            As[kq + 0][row] = v.x;
            As[kq + 1][row] = v.y;
            As[kq + 2][row] = v.z;
            As[kq + 3][row] = v.w;
        }
        // Load B tile: 8 k-rows x 64 cols (128 float4, threads 0..127)
        if (tid < 128) {
            int row = tid >> 4;                 // 0..7
            int nq = (tid & 15) * 4;            // 0..60
            *(float4*)&Bs[row][nq] =
                *(const float4*)&W[(size_t)(kt + row) * N_ + n0 + nq];
        }
        __syncthreads();

        // k strictly ascending, one chain-accumulator per element.
#pragma unroll
        for (int kk = 0; kk < 8; kk++) {
            float a[8], bb[4];
            *(float4*)&a[0] = *(const float4*)&As[kk][ty * 8];
            *(float4*)&a[4] = *(const float4*)&As[kk][ty * 8 + 4];
            *(float4*)&bb[0] = *(const float4*)&Bs[kk][tx * 4];
#pragma unroll
            for (int i = 0; i < 8; i++)
#pragma unroll
                for (int j = 0; j < 4; j++)
                    blk[i][j] = fmaf(a[i], bb[j], blk[i][j]);
        }
        __syncthreads();
    }

    // Final combine (chain0 + chain1) + store (no bias here)
#pragma unroll
    for (int i = 0; i < 8; i++) {
        int m = m0 + ty * 8 + i;
        int orow = remap ? ((m & (SSZ - 1)) * BSZ + (m >> 10)) : m;
        float4 v;
        v.x = __fadd_rn(tot[i][0], blk[i][0]);
        v.y = __fadd_rn(tot[i][1], blk[i][1]);
        v.z = __fadd_rn(tot[i][2], blk[i][2]);
        v.w = __fadd_rn(tot[i][3], blk[i][3]);
        *(float4*)&C[(size_t)orow * N_ + n0 + tx * 4] = v;
    }
}

// ---------------------------------------------------------------------------
// Persistent recurrent kernel: for t in 0..S-1:
//     h_t = xla_tanh((Z_t + splitK2(h_{t-1} @ U)) + b)
// grid = 128 CTAs (one per 8 output columns), block = 256 threads,
// one output element (b, c0+c) per thread.
// The two 512-length chains run in the two lanes of fma.rn.f32x2:
//   lane0: k = 0..511 ascending, lane1: k = 512..1023 ascending,
// then s_tot = s0 + s1 (rn). Operands come pre-paired:
//   h from g_hp (paired layout, written by the scan itself, parity buffered)
//   U from SMEM Usp[c][j] = (U[j][c], U[j+512][c])
// All cross-step-shared reads use __ldcg (L2) — L1 not coherent across CTAs.
// ---------------------------------------------------------------------------
__global__ __launch_bounds__(256, 1) void rnn_kernel(
    int z_sel, const float* __restrict__ U, const float* __restrict__ bias,
    float* H_ext, int h_is_ext, long hStrideT, long hStrideB)
{
    const float* Z = z_sel ? (const float*)g_buf1 : (const float*)g_buf0;
    float* H = h_is_ext ? H_ext : g_buf0;

    __shared__ __align__(16) float2 Usp[8][516];   // [c][j] pairs, padded row

    const int tid = threadIdx.x;
    const int c0 = blockIdx.x * 8;

    // Stage paired U slice: Usp[c][j] = (U[j*D + c0+c], U[(j+512)*D + c0+c])
    for (int i = tid; i < 8 * 512; i += 256) {
        int c = i & 7;
        int j = i >> 3;
        float2 pr;
        pr.x = U[(size_t)j * DSZ + c0 + c];
        pr.y = U[(size_t)(j + 512) * DSZ + c0 + c];
        Usp[c][j] = pr;
    }
    __syncthreads();

    const int w = tid >> 5;
    const int lane = tid & 31;
    const int b = w * 4 + (lane >> 3);   // 0..31
    const int c = lane & 7;              // 0..7
    const int cg = c0 + c;               // global column 0..1023

    const float bval = bias[cg];
    const unsigned nblocks = gridDim.x;
    // paired-store slot for this thread's output (uniform branch per CTA)
    const int pslot = (cg < 512) ? (2 * cg) : (2 * (cg - 512) + 1);

    for (int t = 0; t < SSZ; ++t) {
        float zW = __ldcg(&Z[((size_t)t * BSZ + b) * DSZ + cg]);
        float s_tot = 0.f;
        if (t > 0) {
            const ulonglong2* hb =
                (const ulonglong2*)&g_hp[(t - 1) & 1][b][0];      // 256 x 16B
            const ulonglong2* up = (const ulonglong2*)&Usp[c][0];
            ull s01 = 0;
#pragma unroll 4
            for (int q = 0; q < 256; q++) {
                ulonglong2 hv = __ldcg(hb + q);   // pairs (2q), (2q+1)
                ulonglong2 uv = up[q];
                s01 = fma2(hv.x, uv.x, s01);
                s01 = fma2(hv.y, uv.y, s01);
            }
            float s0, s1;
            unpack2(s01, s0, s1);
            s_tot = __fadd_rn(s0, s1);            // split-K combine p0 + p1
        }
        float z = __fadd_rn(__fadd_rn(zW, s_tot), bval);  // (dot1+dot2)+b
        float hv = xla_tanh(z);
        // normal layout (consumed by next GEMM / final output)
        H[(size_t)t * hStrideT + (size_t)b * hStrideB + cg] = hv;
        // paired layout for the next step's FFMA2 dot
        g_hp[t & 1][b][pslot] = hv;

        if (t != SSZ - 1) {
            // Grid barrier: release value = t+1 (monotonic within launch).
            __syncthreads();
            if (tid == 0) {
                __threadfence();
                unsigned prev = atomicAdd(&g_bar_count, 1u);
                if (prev == nblocks - 1u) {
                    atomicExch(&g_bar_count, 0u);   // reset BEFORE release
                    __threadfence();
                    atomicExch(&g_bar_flag, (unsigned)(t + 1));
                } else {
                    unsigned want = (unsigned)(t + 1);
                    unsigned f;
                    do {
                        asm volatile("ld.acquire.gpu.u32 %0, [%1];"
                                     : "=r"(f) : "l"(&g_bar_flag) : "memory");
                    } while (f < want);
                }
                __threadfence();
            }
            __syncthreads();
        }
    }

    // Final arrive: last CTA restores barrier state to zero for graph replay.
    __syncthreads();
    if (tid == 0) {
        __threadfence();
        unsigned prev = atomicAdd(&g_bar_count, 1u);
        if (prev == nblocks - 1u) {
            atomicExch(&g_bar_count, 0u);
            __threadfence();
            atomicExch(&g_bar_flag, 0u);
        }
    }
}

// ---------------------------------------------------------------------------
// Launch: Z0 = x@W0  ->  scan layer0  ->  Z1 = h0@W1  ->  scan layer1
// ---------------------------------------------------------------------------
extern "C" void kernel_launch(void* const* d_in, const int* in_sizes, int n_in,
                              void* d_out, int out_size)
{
    const float* x  = (const float*)d_in[0];   // [B,S,D]
    const float* Wh = (const float*)d_in[1];   // [L,D,D]
    const float* Uh = (const float*)d_in[2];   // [L,D,D]
    const float* bb = (const float*)d_in[3];   // [L,D]
    float* out = (float*)d_out;                // [B,S,D]

    const int DD = DSZ * DSZ;
    dim3 ggrid(DSZ / 64, (BSZ * SSZ) / 128);   // (16, 256)

    // Layer 0: Z0 = x @ W0 (remap rows to time-major), into buf0
    gemm_kernel<<<ggrid, 256>>>(x, /*a_sel=*/-1, Wh, /*c_sel=*/0, /*remap=*/1);

    // Layer 0 scan: h0_t = tanh((Z0_t + h0_{t-1}@U0) + b0), in place in buf0
    rnn_kernel<<<128, 256>>>(/*z_sel=*/0, Uh, bb, nullptr, /*h_is_ext=*/0,
                             (long)(BSZ * DSZ), (long)DSZ);

    // Layer 1: Z1 = h0 @ W1 (rows already time-major), into buf1
    gemm_kernel<<<ggrid, 256>>>(nullptr, /*a_sel=*/0, Wh + DD,
                                /*c_sel=*/1, /*remap=*/0);

    // Layer 1 scan: out_t = tanh((Z1_t + out_{t-1}@U1) + b1), to d_out [B,S,D]
    rnn_kernel<<<128, 256>>>(/*z_sel=*/1, Uh + DD, bb + DSZ, out, /*h_is_ext=*/1,
                             (long)DSZ, (long)((size_t)SSZ * DSZ));
}